// round 1
// baseline (speedup 1.0000x reference)
#include <cuda_runtime.h>

// ---------------- problem constants (match reference) ----------------
#define N_ATOMS     20000
#define N_EDGES     640000
#define N_ANG_EDGES 160000
#define N_PAIRS     560000
#define N_FEAT      407        // 87 onehot + 64 radial + 256 angular

// radial: shiftR_j = 0.8 + j*0.275, j=0..15 ; eta=16 ; 0.25*exp(-eta x^2)*sw
// angular: shiftA_a = 0.8 + a*0.675, a=0..3 ; eta=8
//          shiftZ_k = pi/8 + k*pi/4,  k=0..3 ; zeta=32

// ---------------- device scratch (allocation-free rule: static globals) ----
__device__ __align__(16) float g_val   [N_ATOMS * 4];        // per-atom valence
__device__ __align__(16) float g_edge  [N_ANG_EDGES * 8];    // {d, sw, v0..v3, pad, pad}
__device__ __align__(16) float g_radial[N_ATOMS * 64];       // radial accumulators
__device__ __align__(16) float g_ang   [N_ATOMS * 256];      // angular accumulators

// ---------------- kernels ----------------

__global__ void k_zero() {
    float4* r = (float4*)g_radial;
    float4* a = (float4*)g_ang;
    int idx = blockIdx.x * blockDim.x + threadIdx.x;
    int stride = gridDim.x * blockDim.x;
    const float4 z = make_float4(0.f, 0.f, 0.f, 0.f);
    for (int i = idx; i < N_ATOMS * 16; i += stride) r[i] = z;
    for (int i = idx; i < N_ATOMS * 64; i += stride) a[i] = z;
}

__global__ void k_prep(const int* __restrict__ species,
                       const float* __restrict__ vtab,
                       const int* __restrict__ ang_dst,
                       const float* __restrict__ ang_d,
                       const float* __restrict__ ang_sw) {
    int idx = blockIdx.x * blockDim.x + threadIdx.x;
    int stride = gridDim.x * blockDim.x;
    for (int t = idx; t < N_ATOMS; t += stride) {
        int sp = species[t];
        ((float4*)g_val)[t] = *(const float4*)(vtab + sp * 4);
    }
    for (int t = idx; t < N_ANG_EDGES; t += stride) {
        int dst = ang_dst[t];
        int sp  = species[dst];
        float4 v = *(const float4*)(vtab + sp * 4);
        float d  = ang_d[t];
        float sw = ang_sw[t];
        ((float4*)g_edge)[t * 2 + 0] = make_float4(d,   sw,  v.x, v.y);
        ((float4*)g_edge)[t * 2 + 1] = make_float4(v.z, v.w, 0.f, 0.f);
    }
}

__global__ void k_radial(const float* __restrict__ dist,
                         const float* __restrict__ sw,
                         const int* __restrict__ src,
                         const int* __restrict__ dst) {
    int e = blockIdx.x * blockDim.x + threadIdx.x;
    if (e >= N_EDGES) return;
    float d = dist[e];
    float s = sw[e];
    int a_src = src[e];
    float4 v = ((const float4*)g_val)[dst[e]];

    // Gaussian window: only bins with 16*(d-shift)^2 <= ~18 matter.
    const float inv_step = 1.0f / 0.275f;
    float t = (d - 0.8f) * inv_step;
    int j0 = (int)ceilf(t - 3.857f);
    if (j0 < 0) j0 = 0;

    float4* outp = (float4*)(g_radial + a_src * 64);
    #pragma unroll
    for (int jj = 0; jj < 9; jj++) {
        int j = j0 + jj;
        if (j > 15) break;
        float x = d - (0.8f + 0.275f * (float)j);
        float term = 0.25f * s * __expf(-16.0f * x * x);
        if (term > 1e-10f) {
            atomicAdd(outp + j, make_float4(term * v.x, term * v.y,
                                            term * v.z, term * v.w));
        }
    }
}

__global__ void k_angular(const float* __restrict__ angles,
                          const int* __restrict__ asrc,
                          const int* __restrict__ adst,
                          const int* __restrict__ catom) {
    int p = blockIdx.x * blockDim.x + threadIdx.x;
    if (p >= N_PAIRS) return;

    int ea = asrc[p];
    int eb = adst[p];
    float4 A0 = ((const float4*)g_edge)[ea * 2 + 0];
    float4 A1 = ((const float4*)g_edge)[ea * 2 + 1];
    float4 B0 = ((const float4*)g_edge)[eb * 2 + 0];
    float4 B1 = ((const float4*)g_edge)[eb * 2 + 1];

    float d12 = 0.5f * (A0.x + B0.x);
    float swp = 2.0f * A0.y * B0.y;

    float vA[4] = {A0.z, A0.w, A1.x, A1.y};
    float vB[4] = {B0.z, B0.w, B1.x, B1.y};
    float vp[4], vm[4];
    #pragma unroll
    for (int i = 0; i < 4; i++) { vp[i] = vA[i] + vB[i]; vm[i] = vA[i] * vB[i]; }

    // factor1[k] = (0.5 + 0.5*cos(theta - shiftZ_k))^32 via angle addition + squarings
    float sn, cs;
    __sincosf(angles[p], &sn, &cs);
    const float CZ[4] = { 0.92387953f,  0.38268343f, -0.38268343f, -0.92387953f};
    const float SZ[4] = { 0.38268343f,  0.92387953f,  0.92387953f,  0.38268343f};
    float f1[4];
    #pragma unroll
    for (int k = 0; k < 4; k++) {
        float u = 0.5f + 0.5f * (cs * CZ[k] + sn * SZ[k]);
        float u2 = u * u, u4 = u2 * u2, u8 = u4 * u4, u16 = u8 * u8;
        f1[k] = u16 * u16;
    }
    // factor2[a] = exp(-8*(d12 - shiftA_a)^2)
    float f2[4];
    #pragma unroll
    for (int a = 0; a < 4; a++) {
        float x = d12 - (0.8f + 0.675f * (float)a);
        f2[a] = __expf(-8.0f * x * x);
    }

    int c = catom[p];
    float4* base = (float4*)(g_ang + c * 256);
    #pragma unroll
    for (int a = 0; a < 4; a++) {
        #pragma unroll
        for (int k = 0; k < 4; k++) {
            float term = swp * f1[k] * f2[a];
            if (term > 1e-8f) {
                float4* o = base + (a * 4 + k) * 4;   // feature block (a*4+k)*16
                #pragma unroll
                for (int i = 0; i < 4; i++) {
                    float ti = term * vp[i];
                    atomicAdd(o + i, make_float4(ti * vm[0], ti * vm[1],
                                                 ti * vm[2], ti * vm[3]));
                }
            }
        }
    }
}

__global__ void k_final(const int* __restrict__ species,
                        float* __restrict__ out) {
    const int n = N_ATOMS * N_FEAT;
    int idx = blockIdx.x * blockDim.x + threadIdx.x;
    int stride = gridDim.x * blockDim.x;
    for (int i = idx; i < n; i += stride) {
        int atom = i / N_FEAT;
        int col  = i - atom * N_FEAT;
        float v;
        if (col < 87) {
            v = (col == species[atom]) ? 1.0f : 0.0f;
        } else if (col < 151) {
            v = g_radial[atom * 64 + (col - 87)];
        } else {
            v = g_ang[atom * 256 + (col - 151)];
        }
        out[i] = v;
    }
}

// ---------------- launcher ----------------
extern "C" void kernel_launch(void* const* d_in, const int* in_sizes, int n_in,
                              void* d_out, int out_size) {
    const int*   species = (const int*)  d_in[0];
    const float* dist    = (const float*)d_in[1];
    const float* swch    = (const float*)d_in[2];
    const int*   esrc    = (const int*)  d_in[3];
    const int*   edst    = (const int*)  d_in[4];
    const float* ang     = (const float*)d_in[5];
    const float* adist   = (const float*)d_in[6];
    const float* asw     = (const float*)d_in[7];
    const int*   aedst   = (const int*)  d_in[8];
    const int*   pasrc   = (const int*)  d_in[9];
    const int*   padst   = (const int*)  d_in[10];
    const int*   catom   = (const int*)  d_in[11];
    const float* vtab    = (const float*)d_in[12];
    float* out = (float*)d_out;

    k_zero<<<1184, 256>>>();
    k_prep<<<640, 256>>>(species, vtab, aedst, adist, asw);
    k_radial<<<(N_EDGES + 255) / 256, 256>>>(dist, swch, esrc, edst);
    k_angular<<<(N_PAIRS + 255) / 256, 256>>>(ang, pasrc, padst, catom);
    k_final<<<2048, 256>>>(species, out);
}